// round 10
// baseline (speedup 1.0000x reference)
#include <cuda_runtime.h>
#include <cuda_bf16.h>

// BlockAttnRes: per-token block attention over N=9 source rows of D=512.
//   score_n = dot(src_n, w) / sqrt(mean(src_n^2)+1e-6),  alpha = softmax(score),
//   h = sum_n alpha_n * src_n.
//
// R10 = R9 (one CTA/token, register-resident rows, __ldcs/__stcs streaming
// hints, 64 regs) with the SECOND BARRIER REMOVED: after the single
// cross-warp reduction barrier, EVERY warp computes the 9-wide softmax on
// its lanes 0-8 (4x redundancy, 2 MUFU/lane) and distributes alphas via
// intra-warp shuffles instead of a smem round-trip + second __syncthreads.
// Warps are fully independent after one barrier -> shorter critical path,
// better tail drain at CTA retirement.

#define NN 9
#define DD 512
#define THREADS 128

__global__ __launch_bounds__(THREADS)
void blockattn_kernel(const float* __restrict__ src,
                      const float* __restrict__ queries,
                      const int*   __restrict__ layer_idx,
                      float*       __restrict__ out)
{
    const int tid  = threadIdx.x;
    const int lane = tid & 31;
    const int warp = tid >> 5;

    const long long token = blockIdx.x;
    const float4* base = reinterpret_cast<const float4*>(src + token * (long long)(NN * DD));

    // Query row (L2-resident, broadcast across all CTAs) — cached load
    const int li = *layer_idx;
    const float4 w4 = reinterpret_cast<const float4*>(queries + (long long)li * DD)[tid];

    // ---- Phase 1: load all 9 rows into registers (streaming, coalesced) ----
    float4 v[NN];
#pragma unroll
    for (int n = 0; n < NN; n++)
        v[n] = __ldcs(base + n * (DD / 4) + tid);

    // ---- Per-thread partials: sum of squares & dot with w, per row ----
    float ss[NN], dt[NN];
#pragma unroll
    for (int n = 0; n < NN; n++) {
        const float4 a = v[n];
        ss[n] = a.x * a.x + a.y * a.y + a.z * a.z + a.w * a.w;
        dt[n] = a.x * w4.x + a.y * w4.y + a.z * w4.z + a.w * w4.w;
    }

    // ---- Warp reduction ----
#pragma unroll
    for (int n = 0; n < NN; n++) {
#pragma unroll
        for (int o = 16; o > 0; o >>= 1) {
            ss[n] += __shfl_xor_sync(0xffffffffu, ss[n], o);
            dt[n] += __shfl_xor_sync(0xffffffffu, dt[n], o);
        }
    }

    // ---- Cross-warp reduction via shared (single barrier) ----
    __shared__ float s_ss[NN][4];
    __shared__ float s_dt[NN][4];

    if (lane == 0) {
#pragma unroll
        for (int n = 0; n < NN; n++) {
            s_ss[n][warp] = ss[n];
            s_dt[n][warp] = dt[n];
        }
    }
    __syncthreads();   // the ONLY barrier

    // ---- Per-warp softmax: lane n owns row n (4x redundant, no 2nd barrier) ----
    float e = 0.0f;
    {
        float sc = -3.4e38f;
        if (lane < NN) {
            const float S  = s_ss[lane][0] + s_ss[lane][1] + s_ss[lane][2] + s_ss[lane][3];
            const float Dt = s_dt[lane][0] + s_dt[lane][1] + s_dt[lane][2] + s_dt[lane][3];
            sc = Dt * rsqrtf(S * (1.0f / DD) + 1e-6f);
        }
        float mx = sc;
#pragma unroll
        for (int o = 16; o > 0; o >>= 1)
            mx = fmaxf(mx, __shfl_xor_sync(0xffffffffu, mx, o));

        e = (lane < NN) ? __expf(sc - mx) : 0.0f;
        float sum = e;
#pragma unroll
        for (int o = 16; o > 0; o >>= 1)
            sum += __shfl_xor_sync(0xffffffffu, sum, o);

        e /= sum;   // lane n holds alpha_n for n<9; garbage elsewhere (unused)
    }

    // ---- Phase 2: weighted sum; alphas broadcast via intra-warp shuffles ----
    float4 o = make_float4(0.f, 0.f, 0.f, 0.f);
#pragma unroll
    for (int n = 0; n < NN; n++) {
        const float a = __shfl_sync(0xffffffffu, e, n);
        o.x += a * v[n].x;
        o.y += a * v[n].y;
        o.z += a * v[n].z;
        o.w += a * v[n].w;
    }

    __stcs(reinterpret_cast<float4*>(out + token * (long long)DD) + tid, o);
}

extern "C" void kernel_launch(void* const* d_in, const int* in_sizes, int n_in,
                              void* d_out, int out_size)
{
    const float* src     = (const float*)d_in[0];
    const float* queries = (const float*)d_in[1];
    const int*   lidx    = (const int*)d_in[2];
    float*       out     = (float*)d_out;

    const int tokens = in_sizes[0] / (NN * DD);   // B*T = 32768
    blockattn_kernel<<<tokens, THREADS>>>(src, queries, lidx, out);
}